// round 2
// baseline (speedup 1.0000x reference)
#include <cuda_runtime.h>
#include <cstdint>

#define NXI 62        // inner points
#define NP  64        // padded row stride for P

// Scratch for the propagator P = (M^T)^100, padded to 62x64 (cols 62,63 = 0)
__device__ float g_P[NXI * NP];

__device__ __forceinline__ unsigned long long fma2(unsigned long long a,
                                                   unsigned long long b,
                                                   unsigned long long c) {
    unsigned long long d;
    asm("fma.rn.f32x2 %0, %1, %2, %3;" : "=l"(d) : "l"(a), "l"(b), "l"(c));
    return d;
}

// ---------------------------------------------------------------------------
// Kernel 1: P = (M^T)^100 via square-and-multiply (8 small matmuls), 1 CTA.
// 100 = 0b1100100 -> start R=B, bits {1,0,0,1,0,0}: sq[,mul] sequence.
// ---------------------------------------------------------------------------
__global__ __launch_bounds__(1024) void precompute_kernel(const float* __restrict__ M) {
    __shared__ __align__(16) float bufA[NXI * NP];
    __shared__ __align__(16) float bufB[NXI * NP];   // base = M^T (padded)
    __shared__ __align__(16) float bufC[NXI * NP];

    const int tid = threadIdx.x;

    for (int idx = tid; idx < NXI * NP; idx += 1024) {
        int i = idx >> 6, j = idx & 63;
        float v = (j < NXI) ? M[j * NXI + i] : 0.0f;   // transpose load
        bufA[idx] = v;
        bufB[idx] = v;
    }
    __syncthreads();

    float* cur = bufA;
    float* tmp = bufC;

    const int bits[6] = {1, 0, 0, 1, 0, 0};

#define MATMUL(Aa, Bb, Cc)                                                  \
    do {                                                                    \
        if (tid < 992) {                                                    \
            int i = tid >> 4, q = tid & 15;                                 \
            float4 acc = make_float4(0.f, 0.f, 0.f, 0.f);                   \
            const float4* B4 = (const float4*)(Bb);                         \
            _Pragma("unroll 8")                                             \
            for (int k = 0; k < NXI; ++k) {                                 \
                float a = (Aa)[i * NP + k];                                 \
                float4 b = B4[k * 16 + q];                                  \
                acc.x += a * b.x; acc.y += a * b.y;                         \
                acc.z += a * b.z; acc.w += a * b.w;                         \
            }                                                               \
            ((float4*)(Cc))[i * 16 + q] = acc;                              \
        }                                                                   \
        __syncthreads();                                                    \
    } while (0)

    for (int b = 0; b < 6; ++b) {
        MATMUL(cur, cur, tmp);                 // square
        { float* s = cur; cur = tmp; tmp = s; }
        if (bits[b]) {
            MATMUL(cur, bufB, tmp);            // multiply by base
            { float* s = cur; cur = tmp; tmp = s; }
        }
    }
#undef MATMUL

    for (int idx = tid; idx < NXI * NP; idx += 1024)
        g_P[idx] = cur[idx];
}

// ---------------------------------------------------------------------------
// Kernel 2: out[r, 1:63] = u0[r, 1:63] @ P ; out[r,0] = out[r,63] = 0.
// One row per thread; 31 packed f32x2 accumulators; P broadcast from SMEM.
// ---------------------------------------------------------------------------
__global__ __launch_bounds__(256) void heat_rowgemm_kernel(
    const float* __restrict__ u0, float* __restrict__ out, int nrows) {

    __shared__ __align__(16) float Ps[NXI * NP];
    for (int idx = threadIdx.x; idx < NXI * NP; idx += 256)
        Ps[idx] = g_P[idx];
    __syncthreads();

    const int row = blockIdx.x * 256 + threadIdx.x;
    if (row >= nrows) return;

    const double2* Ps2 = (const double2*)Ps;   // 16B lanes: 2x f32x2 per load

    unsigned long long acc[31];
#pragma unroll
    for (int p = 0; p < 31; ++p) acc[p] = 0ull;

    const float4* up = (const float4*)(u0 + (size_t)row * 64);

    // Process input columns 1..62 (k = col-1), streaming float4 chunks.
#pragma unroll
    for (int t = 0; t < 16; ++t) {
        float4 v = up[t];
        float elems[4] = {v.x, v.y, v.z, v.w};
#pragma unroll
        for (int e = 0; e < 4; ++e) {
            int col = 4 * t + e;
            if (col == 0 || col == 63) continue;   // compile-time pruned
            int k = col - 1;
            unsigned long long uu;
            asm("mov.b64 %0, {%1, %1};" : "=l"(uu) : "r"(__float_as_uint(elems[e])));
            const double2* rp = Ps2 + k * 16;
#pragma unroll
            for (int q = 0; q < 16; ++q) {
                double2 b = rp[q];
                acc[2 * q] = fma2(uu, __double_as_longlong(b.x), acc[2 * q]);
                if (q < 15)
                    acc[2 * q + 1] = fma2(uu, __double_as_longlong(b.y), acc[2 * q + 1]);
            }
        }
    }

    float ov[64];
    ov[0] = 0.0f;
    ov[63] = 0.0f;
#pragma unroll
    for (int p = 0; p < 31; ++p) {
        unsigned lo, hi;
        asm("mov.b64 {%0, %1}, %2;" : "=r"(lo), "=r"(hi) : "l"(acc[p]));
        ov[2 * p + 1] = __uint_as_float(lo);
        ov[2 * p + 2] = __uint_as_float(hi);
    }

    float4* op = (float4*)(out + (size_t)row * 64);
#pragma unroll
    for (int t = 0; t < 16; ++t)
        op[t] = make_float4(ov[4 * t], ov[4 * t + 1], ov[4 * t + 2], ov[4 * t + 3]);
}

// ---------------------------------------------------------------------------
extern "C" void kernel_launch(void* const* d_in, const int* in_sizes, int n_in,
                              void* d_out, int out_size) {
    const float* u0 = (const float*)d_in[0];
    const float* M  = (const float*)d_in[1];
    int u0_elems = in_sizes[0];
    if (n_in >= 2 && in_sizes[0] == NXI * NXI) {   // defensive input-order check
        u0 = (const float*)d_in[1];
        M  = (const float*)d_in[0];
        u0_elems = in_sizes[1];
    }
    const int nrows = u0_elems / 64;

    precompute_kernel<<<1, 1024>>>(M);

    const int grid = (nrows + 255) / 256;
    heat_rowgemm_kernel<<<grid, 256>>>(u0, (float*)d_out, nrows);
}

// round 3
// speedup vs baseline: 1.0023x; 1.0023x over previous
#include <cuda_runtime.h>
#include <cstdint>

#define NXI 62        // inner points
#define NP  64        // padded row stride for P

// Scratch for the propagator P = (M^T)^100, padded to 62x64 (cols 62,63 = 0)
__device__ float g_P[NXI * NP];

__device__ __forceinline__ unsigned long long fma2(unsigned long long a,
                                                   unsigned long long b,
                                                   unsigned long long c) {
    unsigned long long d;
    asm("fma.rn.f32x2 %0, %1, %2, %3;" : "=l"(d) : "l"(a), "l"(b), "l"(c));
    return d;
}

// ---------------------------------------------------------------------------
// Kernel 1: P = (M^T)^100 via square-and-multiply (8 small matmuls), 1 CTA.
// 100 = 0b1100100 -> start R=B, bits {1,0,0,1,0,0}: sq[,mul] sequence.
// ---------------------------------------------------------------------------
__global__ __launch_bounds__(1024) void precompute_kernel(const float* __restrict__ M) {
    __shared__ __align__(16) float bufA[NXI * NP];
    __shared__ __align__(16) float bufB[NXI * NP];   // base = M^T (padded)
    __shared__ __align__(16) float bufC[NXI * NP];

    const int tid = threadIdx.x;

    for (int idx = tid; idx < NXI * NP; idx += 1024) {
        int i = idx >> 6, j = idx & 63;
        float v = (j < NXI) ? M[j * NXI + i] : 0.0f;   // transpose load
        bufA[idx] = v;
        bufB[idx] = v;
    }
    __syncthreads();

    float* cur = bufA;
    float* tmp = bufC;

    const int bits[6] = {1, 0, 0, 1, 0, 0};

#define MATMUL(Aa, Bb, Cc)                                                  \
    do {                                                                    \
        if (tid < 992) {                                                    \
            int i = tid >> 4, q = tid & 15;                                 \
            float4 acc = make_float4(0.f, 0.f, 0.f, 0.f);                   \
            const float4* B4 = (const float4*)(Bb);                         \
            _Pragma("unroll 8")                                             \
            for (int k = 0; k < NXI; ++k) {                                 \
                float a = (Aa)[i * NP + k];                                 \
                float4 b = B4[k * 16 + q];                                  \
                acc.x += a * b.x; acc.y += a * b.y;                         \
                acc.z += a * b.z; acc.w += a * b.w;                         \
            }                                                               \
            ((float4*)(Cc))[i * 16 + q] = acc;                              \
        }                                                                   \
        __syncthreads();                                                    \
    } while (0)

    for (int b = 0; b < 6; ++b) {
        MATMUL(cur, cur, tmp);                 // square
        { float* s = cur; cur = tmp; tmp = s; }
        if (bits[b]) {
            MATMUL(cur, bufB, tmp);            // multiply by base
            { float* s = cur; cur = tmp; tmp = s; }
        }
    }
#undef MATMUL

    for (int idx = tid; idx < NXI * NP; idx += 1024)
        g_P[idx] = cur[idx];
}

// ---------------------------------------------------------------------------
// Kernel 2: out[r, 1:63] = u0[r, 1:63] @ P ; out[r,0] = out[r,63] = 0.
// One row per thread; 31 packed f32x2 accumulators; P broadcast from SMEM.
// ---------------------------------------------------------------------------
__global__ __launch_bounds__(256) void heat_rowgemm_kernel(
    const float* __restrict__ u0, float* __restrict__ out, int nrows) {

    __shared__ __align__(16) float Ps[NXI * NP];
    for (int idx = threadIdx.x; idx < NXI * NP; idx += 256)
        Ps[idx] = g_P[idx];
    __syncthreads();

    const int row = blockIdx.x * 256 + threadIdx.x;
    if (row >= nrows) return;

    const double2* Ps2 = (const double2*)Ps;   // 16B lanes: 2x f32x2 per load

    unsigned long long acc[31];
#pragma unroll
    for (int p = 0; p < 31; ++p) acc[p] = 0ull;

    const float4* up = (const float4*)(u0 + (size_t)row * 64);

    // Process input columns 1..62 (k = col-1), streaming float4 chunks.
#pragma unroll
    for (int t = 0; t < 16; ++t) {
        float4 v = up[t];
        float elems[4] = {v.x, v.y, v.z, v.w};
#pragma unroll
        for (int e = 0; e < 4; ++e) {
            int col = 4 * t + e;
            if (col == 0 || col == 63) continue;   // compile-time pruned
            int k = col - 1;
            unsigned long long uu;
            asm("mov.b64 %0, {%1, %1};" : "=l"(uu) : "r"(__float_as_uint(elems[e])));
            const double2* rp = Ps2 + k * 16;
#pragma unroll
            for (int q = 0; q < 16; ++q) {
                double2 b = rp[q];
                acc[2 * q] = fma2(uu, __double_as_longlong(b.x), acc[2 * q]);
                if (q < 15)
                    acc[2 * q + 1] = fma2(uu, __double_as_longlong(b.y), acc[2 * q + 1]);
            }
        }
    }

    float ov[64];
    ov[0] = 0.0f;
    ov[63] = 0.0f;
#pragma unroll
    for (int p = 0; p < 31; ++p) {
        unsigned lo, hi;
        asm("mov.b64 {%0, %1}, %2;" : "=r"(lo), "=r"(hi) : "l"(acc[p]));
        ov[2 * p + 1] = __uint_as_float(lo);
        ov[2 * p + 2] = __uint_as_float(hi);
    }

    float4* op = (float4*)(out + (size_t)row * 64);
#pragma unroll
    for (int t = 0; t < 16; ++t)
        op[t] = make_float4(ov[4 * t], ov[4 * t + 1], ov[4 * t + 2], ov[4 * t + 3]);
}

// ---------------------------------------------------------------------------
extern "C" void kernel_launch(void* const* d_in, const int* in_sizes, int n_in,
                              void* d_out, int out_size) {
    const float* u0 = (const float*)d_in[0];
    const float* M  = (const float*)d_in[1];
    int u0_elems = in_sizes[0];
    if (n_in >= 2 && in_sizes[0] == NXI * NXI) {   // defensive input-order check
        u0 = (const float*)d_in[1];
        M  = (const float*)d_in[0];
        u0_elems = in_sizes[1];
    }
    const int nrows = u0_elems / 64;

    precompute_kernel<<<1, 1024>>>(M);

    const int grid = (nrows + 255) / 256;
    heat_rowgemm_kernel<<<grid, 256>>>(u0, (float*)d_out, nrows);
}

// round 4
// speedup vs baseline: 1.2782x; 1.2753x over previous
#include <cuda_runtime.h>
#include <cstdint>

#define NXI 62        // inner points (K of the GEMM)
#define NP  64        // padded row stride for P (shifted layout, 64 output cols)
#define US  192       // u_s row stride: 16 groups of 8 floats padded to 12
#define BM  128       // rows per CTA
#define THREADS 128   // 16 row-threads x 8 col-threads

// Propagator, SHIFTED: g_P[k*64 + c] = P[k][c-1] for c in 1..62, cols 0 & 63 = 0.
__device__ float g_P[NXI * NP];

__device__ __forceinline__ unsigned long long fma2(unsigned long long a,
                                                   unsigned long long b,
                                                   unsigned long long c) {
    unsigned long long d;
    asm("fma.rn.f32x2 %0, %1, %2, %3;" : "=l"(d) : "l"(a), "l"(b), "l"(c));
    return d;
}

// ---------------------------------------------------------------------------
// Kernel 1: P = (M^T)^100 via square-and-multiply (8 small matmuls), 1 CTA.
// ---------------------------------------------------------------------------
__global__ __launch_bounds__(1024) void precompute_kernel(const float* __restrict__ M) {
    __shared__ __align__(16) float bufA[NXI * NP];
    __shared__ __align__(16) float bufB[NXI * NP];   // base = M^T (padded)
    __shared__ __align__(16) float bufC[NXI * NP];

    const int tid = threadIdx.x;

    for (int idx = tid; idx < NXI * NP; idx += 1024) {
        int i = idx >> 6, j = idx & 63;
        float v = (j < NXI) ? M[j * NXI + i] : 0.0f;   // transpose load
        bufA[idx] = v;
        bufB[idx] = v;
    }
    __syncthreads();

    float* cur = bufA;
    float* tmp = bufC;

    const int bits[6] = {1, 0, 0, 1, 0, 0};

#define MATMUL(Aa, Bb, Cc)                                                  \
    do {                                                                    \
        if (tid < 992) {                                                    \
            int i = tid >> 4, q = tid & 15;                                 \
            float4 acc = make_float4(0.f, 0.f, 0.f, 0.f);                   \
            const float4* B4 = (const float4*)(Bb);                         \
            _Pragma("unroll 8")                                             \
            for (int k = 0; k < NXI; ++k) {                                 \
                float a = (Aa)[i * NP + k];                                 \
                float4 b = B4[k * 16 + q];                                  \
                acc.x += a * b.x; acc.y += a * b.y;                         \
                acc.z += a * b.z; acc.w += a * b.w;                         \
            }                                                               \
            ((float4*)(Cc))[i * 16 + q] = acc;                              \
        }                                                                   \
        __syncthreads();                                                    \
    } while (0)

    for (int b = 0; b < 6; ++b) {
        MATMUL(cur, cur, tmp);                 // square
        { float* s = cur; cur = tmp; tmp = s; }
        if (bits[b]) {
            MATMUL(cur, bufB, tmp);            // multiply by base
            { float* s = cur; cur = tmp; tmp = s; }
        }
    }
#undef MATMUL

    // Store SHIFTED: g_P[i][c] = P[i][c-1], c in 1..62; cols 0 and 63 = 0.
    for (int idx = tid; idx < NXI * NP; idx += 1024) {
        int i = idx >> 6, c = idx & 63;
        float v = (c >= 1 && c <= 62) ? cur[i * NP + (c - 1)] : 0.0f;
        g_P[idx] = v;
    }
}

// ---------------------------------------------------------------------------
// Kernel 2: 2D-register-tiled GEMM. CTA = 128 rows x 64 cols; thread = 8x8.
//   out[r][c] = sum_k u0[r][k+1] * g_P[k][c]   (g_P shifted; cols 0,63 -> 0)
// ---------------------------------------------------------------------------
extern __shared__ float smem_dyn[];

__global__ __launch_bounds__(THREADS, 3) void heat_gemm_kernel(
    const float* __restrict__ u0, float* __restrict__ out, int nrows) {

    float* Ps = smem_dyn;              // [NXI * NP]   = 15,872 B
    float* Us = smem_dyn + NXI * NP;   // [NXI * US]   = 47,616 B (also out staging)

    const int tid = threadIdx.x;
    const long long blockRow = (long long)blockIdx.x * BM;

    // ---- stage P (from global, hot in L2) ----
    for (int i = tid; i < NXI * NP / 4; i += THREADS)
        ((float4*)Ps)[i] = ((const float4*)g_P)[i];

    // ---- stage u transposed: Us[k][row], row groups of 8 padded to 12 ----
    {
        long long r = blockRow + tid;
        if (r >= nrows) r = nrows - 1;   // clamp (nrows divisible by 128 in practice)
        const float4* gp = (const float4*)(u0 + r * 64);
        const int rbase = (tid >> 3) * 12 + (tid & 7);
#pragma unroll
        for (int j = 0; j < 16; ++j) {
            float4 q = gp[j];
            int c = 4 * j;                       // q.x=col c, ..., q.w=col c+3
            if (c != 0)      Us[(c - 1) * US + rbase] = q.x;   // skip col 0
            Us[(c + 0) * US + rbase] = q.y;                    // col c+1 -> k=c
            Us[(c + 1) * US + rbase] = q.z;
            if (c + 3 != 63) Us[(c + 2) * US + rbase] = q.w;   // skip col 63
        }
    }
    __syncthreads();

    const int rowth = tid & 15;      // warp: lanes 0-15 rowth, shared by 2 colth
    const int colth = tid >> 4;

    unsigned long long A[8][4];
#pragma unroll
    for (int i = 0; i < 8; ++i)
#pragma unroll
        for (int j = 0; j < 4; ++j) A[i][j] = 0ull;

    const float* up0 = Us + rowth * 12;
    const float* pp0 = Ps + colth * 8;

#pragma unroll 2
    for (int k = 0; k < NXI; ++k) {
        float4 ua = *(const float4*)(up0 + k * US);
        float4 ub = *(const float4*)(up0 + k * US + 4);
        ulonglong2 Pq0 = *(const ulonglong2*)(pp0 + k * NP);
        ulonglong2 Pq1 = *(const ulonglong2*)(pp0 + k * NP + 4);
        float uu[8] = {ua.x, ua.y, ua.z, ua.w, ub.x, ub.y, ub.z, ub.w};
#pragma unroll
        for (int i = 0; i < 8; ++i) {
            unsigned long long ud;
            asm("mov.b64 %0, {%1, %1};" : "=l"(ud) : "r"(__float_as_uint(uu[i])));
            A[i][0] = fma2(ud, Pq0.x, A[i][0]);
            A[i][1] = fma2(ud, Pq0.y, A[i][1]);
            A[i][2] = fma2(ud, Pq1.x, A[i][2]);
            A[i][3] = fma2(ud, Pq1.y, A[i][3]);
        }
    }

    // ---- epilogue: stage to shared with XOR-swizzled 8-col blocks ----
    __syncthreads();   // done reading Us
    {
        const int sb = (colth ^ (rowth & 7)) * 8;
#pragma unroll
        for (int i = 0; i < 8; ++i) {
            int r = rowth * 8 + i;
            unsigned long long* dst = (unsigned long long*)(Us + r * 64 + sb);
            dst[0] = A[i][0];
            dst[1] = A[i][1];
            dst[2] = A[i][2];
            dst[3] = A[i][3];
        }
    }
    __syncthreads();

    // ---- coalesced global write (de-swizzle on read) ----
    {
        float4* og = (float4*)(out + blockRow * 64);
        long long rows_left = nrows - blockRow;
#pragma unroll
        for (int m = 0; m < 16; ++m) {
            int g = m * THREADS + tid;           // float4 index within tile
            int r = g >> 4, j = g & 15;
            int sb = ((j >> 1) ^ ((r >> 3) & 7)) * 8;
            float4 v = *(const float4*)(Us + r * 64 + sb + (j & 1) * 4);
            if (r < rows_left) og[g] = v;
        }
    }
}

// ---------------------------------------------------------------------------
extern "C" void kernel_launch(void* const* d_in, const int* in_sizes, int n_in,
                              void* d_out, int out_size) {
    const float* u0 = (const float*)d_in[0];
    const float* M  = (const float*)d_in[1];
    int u0_elems = in_sizes[0];
    if (n_in >= 2 && in_sizes[0] == NXI * NXI) {   // defensive input-order check
        u0 = (const float*)d_in[1];
        M  = (const float*)d_in[0];
        u0_elems = in_sizes[1];
    }
    const int nrows = u0_elems / 64;

    static int smem_set = 0;
    const int smem_bytes = (NXI * NP + NXI * US) * (int)sizeof(float);  // 63,488
    if (!smem_set) {
        cudaFuncSetAttribute(heat_gemm_kernel,
                             cudaFuncAttributeMaxDynamicSharedMemorySize, smem_bytes);
        smem_set = 1;
    }

    precompute_kernel<<<1, 1024>>>(M);

    const int grid = (nrows + BM - 1) / BM;
    heat_gemm_kernel<<<grid, THREADS, smem_bytes>>>(u0, (float*)d_out, nrows);
}